// round 12
// baseline (speedup 1.0000x reference)
#include <cuda_runtime.h>
#include <math.h>

// Problem shape (fixed by reference)
#define N_ROWS 262144
#define D_DIM  512
#define V_DIM  512

#define K1_GRID  1024
#define K1_BLOCK 256
#define K1_WARPS_PER_BLOCK (K1_BLOCK / 32)
#define TOTAL_WARPS (K1_GRID * K1_WARPS_PER_BLOCK)   // 8192 -> 32 rows/warp

#define K3_BLOCK 256
#define K3_GRID  (N_ROWS / (K3_BLOCK * 4))           // 256 blocks, 1 float4/thread

#define MAX_TIES 64

// ---- device scratch (no allocations allowed) ----
__device__ float g_logits[N_ROWS];
__device__ float g_blockmax[K1_GRID];
__device__ float g_M;
__device__ float g_Z;
__device__ int   g_tieidx[MAX_TIES];
__device__ int   g_tiecount;

// ---------------------------------------------------------------------------
// K1: logits[i] = keys[i,:] . query   (warp per row, grid-stride, 2-row unroll)
// Also tracks per-block max logit.
// ---------------------------------------------------------------------------
__global__ __launch_bounds__(K1_BLOCK) void k1_logits(
    const float* __restrict__ query,
    const float* __restrict__ keys)
{
    const int lane  = threadIdx.x & 31;
    const int warp  = (blockIdx.x * K1_BLOCK + threadIdx.x) >> 5;

    // Query register-resident: lane l holds q[l*4 + it*128 .. +3] for it=0..3
    const float4* q4 = reinterpret_cast<const float4*>(query);
    float4 q0 = q4[lane];
    float4 q1 = q4[lane + 32];
    float4 q2 = q4[lane + 64];
    float4 q3 = q4[lane + 96];

    float wmax = -INFINITY;

    // 32 rows per warp, processed 2 at a time for memory-level parallelism
    const int rows_per_warp = N_ROWS / TOTAL_WARPS;  // 32
    int row = warp * rows_per_warp;
    #pragma unroll 1
    for (int it = 0; it < rows_per_warp / 2; ++it, row += 2) {
        const float4* ka = reinterpret_cast<const float4*>(keys + (size_t)row * D_DIM);
        const float4* kb = reinterpret_cast<const float4*>(keys + (size_t)(row + 1) * D_DIM);

        float4 a0 = ka[lane];       float4 b0 = kb[lane];
        float4 a1 = ka[lane + 32];  float4 b1 = kb[lane + 32];
        float4 a2 = ka[lane + 64];  float4 b2 = kb[lane + 64];
        float4 a3 = ka[lane + 96];  float4 b3 = kb[lane + 96];

        float sa = 0.f, sb = 0.f;
        sa = fmaf(a0.x, q0.x, sa); sa = fmaf(a0.y, q0.y, sa);
        sa = fmaf(a0.z, q0.z, sa); sa = fmaf(a0.w, q0.w, sa);
        sa = fmaf(a1.x, q1.x, sa); sa = fmaf(a1.y, q1.y, sa);
        sa = fmaf(a1.z, q1.z, sa); sa = fmaf(a1.w, q1.w, sa);
        sa = fmaf(a2.x, q2.x, sa); sa = fmaf(a2.y, q2.y, sa);
        sa = fmaf(a2.z, q2.z, sa); sa = fmaf(a2.w, q2.w, sa);
        sa = fmaf(a3.x, q3.x, sa); sa = fmaf(a3.y, q3.y, sa);
        sa = fmaf(a3.z, q3.z, sa); sa = fmaf(a3.w, q3.w, sa);

        sb = fmaf(b0.x, q0.x, sb); sb = fmaf(b0.y, q0.y, sb);
        sb = fmaf(b0.z, q0.z, sb); sb = fmaf(b0.w, q0.w, sb);
        sb = fmaf(b1.x, q1.x, sb); sb = fmaf(b1.y, q1.y, sb);
        sb = fmaf(b1.z, q1.z, sb); sb = fmaf(b1.w, q1.w, sb);
        sb = fmaf(b2.x, q2.x, sb); sb = fmaf(b2.y, q2.y, sb);
        sb = fmaf(b2.z, q2.z, sb); sb = fmaf(b2.w, q2.w, sb);
        sb = fmaf(b3.x, q3.x, sb); sb = fmaf(b3.y, q3.y, sb);
        sb = fmaf(b3.z, q3.z, sb); sb = fmaf(b3.w, q3.w, sb);

        // warp butterfly reduce (all lanes end with the full sum)
        #pragma unroll
        for (int m = 16; m > 0; m >>= 1) {
            sa += __shfl_xor_sync(0xFFFFFFFFu, sa, m);
            sb += __shfl_xor_sync(0xFFFFFFFFu, sb, m);
        }
        if (lane == 0) {
            g_logits[row]     = sa;
            g_logits[row + 1] = sb;
        }
        wmax = fmaxf(wmax, fmaxf(sa, sb));
    }

    // block max reduce (lane 0 of each warp contributes)
    __shared__ float smax[K1_WARPS_PER_BLOCK];
    if (lane == 0) smax[threadIdx.x >> 5] = wmax;
    __syncthreads();
    if (threadIdx.x == 0) {
        float m = -INFINITY;
        #pragma unroll
        for (int w = 0; w < K1_WARPS_PER_BLOCK; ++w) m = fmaxf(m, smax[w]);
        g_blockmax[blockIdx.x] = m;
    }
}

// ---------------------------------------------------------------------------
// K2: global max over block maxes; reset accumulators (deterministic per launch)
// ---------------------------------------------------------------------------
__global__ __launch_bounds__(256) void k2_max()
{
    __shared__ float sm[256];
    float m = -INFINITY;
    for (int i = threadIdx.x; i < K1_GRID; i += 256)
        m = fmaxf(m, g_blockmax[i]);
    sm[threadIdx.x] = m;
    __syncthreads();
    for (int s = 128; s > 0; s >>= 1) {
        if (threadIdx.x < s)
            sm[threadIdx.x] = fmaxf(sm[threadIdx.x], sm[threadIdx.x + s]);
        __syncthreads();
    }
    if (threadIdx.x == 0) {
        g_M = sm[0];
        g_Z = 0.0f;
        g_tiecount = 0;
    }
}

// ---------------------------------------------------------------------------
// K3: Z = sum exp(logit - M); record indices where logit == M (bit-exact)
// ---------------------------------------------------------------------------
__global__ __launch_bounds__(K3_BLOCK) void k3_sumexp()
{
    const float M = g_M;
    const int i = blockIdx.x * K3_BLOCK + threadIdx.x;   // one float4 per thread
    float4 l = reinterpret_cast<const float4*>(g_logits)[i];

    float s = __expf(l.x - M) + __expf(l.y - M) + __expf(l.z - M) + __expf(l.w - M);

    const int base = i * 4;
    if (l.x == M) { int p = atomicAdd(&g_tiecount, 1); if (p < MAX_TIES) g_tieidx[p] = base + 0; }
    if (l.y == M) { int p = atomicAdd(&g_tiecount, 1); if (p < MAX_TIES) g_tieidx[p] = base + 1; }
    if (l.z == M) { int p = atomicAdd(&g_tiecount, 1); if (p < MAX_TIES) g_tieidx[p] = base + 2; }
    if (l.w == M) { int p = atomicAdd(&g_tiecount, 1); if (p < MAX_TIES) g_tieidx[p] = base + 3; }

    // warp + block reduce, then one atomic per block
    #pragma unroll
    for (int m = 16; m > 0; m >>= 1) s += __shfl_xor_sync(0xFFFFFFFFu, s, m);
    __shared__ float sw[K3_BLOCK / 32];
    if ((threadIdx.x & 31) == 0) sw[threadIdx.x >> 5] = s;
    __syncthreads();
    if (threadIdx.x == 0) {
        float t = 0.f;
        #pragma unroll
        for (int w = 0; w < K3_BLOCK / 32; ++w) t += sw[w];
        atomicAdd(&g_Z, t);
    }
}

// ---------------------------------------------------------------------------
// K4: out[v] = (1/Z) * sum over tied rows of values[row][v]
// ---------------------------------------------------------------------------
__global__ __launch_bounds__(V_DIM) void k4_output(
    const float* __restrict__ values,
    float* __restrict__ out)
{
    const int t = threadIdx.x;
    const float inv = 1.0f / g_Z;
    int cnt = g_tiecount;
    if (cnt > MAX_TIES) cnt = MAX_TIES;
    float acc = 0.f;
    for (int j = 0; j < cnt; ++j)
        acc += values[(size_t)g_tieidx[j] * V_DIM + t];
    out[t] = acc * inv;
}

// ---------------------------------------------------------------------------
extern "C" void kernel_launch(void* const* d_in, const int* in_sizes, int n_in,
                              void* d_out, int out_size)
{
    const float* query  = (const float*)d_in[0];  // [512]
    const float* keys   = (const float*)d_in[1];  // [262144, 512]
    const float* values = (const float*)d_in[2];  // [262144, 512]
    float* out = (float*)d_out;                   // [512]

    k1_logits<<<K1_GRID, K1_BLOCK>>>(query, keys);
    k2_max<<<1, 256>>>();
    k3_sumexp<<<K3_GRID, K3_BLOCK>>>();
    k4_output<<<1, V_DIM>>>(values, out);
}

// round 13
// speedup vs baseline: 1.1431x; 1.1431x over previous
#include <cuda_runtime.h>
#include <math.h>

// Problem shape (fixed by reference)
#define N_ROWS 262144
#define D_DIM  512
#define V_DIM  512

#define GRID   1024
#define BLOCK  256
#define WARPS  (BLOCK / 32)
#define ROWS_PER_WARP (N_ROWS / (GRID * WARPS))   // 32
#define ROWS_PER_ITER 4
#define ITERS (ROWS_PER_WARP / ROWS_PER_ITER)     // 8

#define BTIES     4     // tie indices kept per block
#define MAX_TIES 16     // tie indices kept globally

// ---- device scratch (static zero-init; g_done reset by last block) ----
__device__ float g_blockmax[GRID];
__device__ float g_blocksum[GRID];
__device__ int   g_btiecnt[GRID];
__device__ int   g_btieidx[GRID * BTIES];
__device__ unsigned int g_done;   // zero-initialized; reset to 0 each launch

__device__ __forceinline__ float dot16(float4 a0, float4 a1, float4 a2, float4 a3,
                                       float4 q0, float4 q1, float4 q2, float4 q3)
{
    float s = 0.f;
    s = fmaf(a0.x, q0.x, s); s = fmaf(a0.y, q0.y, s);
    s = fmaf(a0.z, q0.z, s); s = fmaf(a0.w, q0.w, s);
    s = fmaf(a1.x, q1.x, s); s = fmaf(a1.y, q1.y, s);
    s = fmaf(a1.z, q1.z, s); s = fmaf(a1.w, q1.w, s);
    s = fmaf(a2.x, q2.x, s); s = fmaf(a2.y, q2.y, s);
    s = fmaf(a2.z, q2.z, s); s = fmaf(a2.w, q2.w, s);
    s = fmaf(a3.x, q3.x, s); s = fmaf(a3.y, q3.y, s);
    s = fmaf(a3.z, q3.z, s); s = fmaf(a3.w, q3.w, s);
    return s;
}

__global__ __launch_bounds__(BLOCK, 2) void fused_kernel(
    const float* __restrict__ query,
    const float* __restrict__ keys,
    const float* __restrict__ values,
    float* __restrict__ out)
{
    const int tid   = threadIdx.x;
    const int lane  = tid & 31;
    const int wid   = tid >> 5;
    const int gwarp = blockIdx.x * WARPS + wid;
    const int wbase = gwarp * ROWS_PER_WARP;

    // Query register-resident: lane l owns q[16B chunks l, l+32, l+64, l+96]
    const float4* q4 = reinterpret_cast<const float4*>(query);
    const float4 q0 = q4[lane];
    const float4 q1 = q4[lane + 32];
    const float4 q2 = q4[lane + 64];
    const float4 q3 = q4[lane + 96];

    // lane i ends up holding the logit of row (wbase + i)
    float mylogit = -INFINITY;

    int row = wbase;
    #pragma unroll 1
    for (int it = 0; it < ITERS; ++it, row += ROWS_PER_ITER) {
        const float4* kr0 = reinterpret_cast<const float4*>(keys + (size_t)(row + 0) * D_DIM);
        const float4* kr1 = reinterpret_cast<const float4*>(keys + (size_t)(row + 1) * D_DIM);
        const float4* kr2 = reinterpret_cast<const float4*>(keys + (size_t)(row + 2) * D_DIM);
        const float4* kr3 = reinterpret_cast<const float4*>(keys + (size_t)(row + 3) * D_DIM);

        // 16 LDG.128 issued up front -> high MLP
        float4 a0 = kr0[lane], a1 = kr0[lane + 32], a2 = kr0[lane + 64], a3 = kr0[lane + 96];
        float4 b0 = kr1[lane], b1 = kr1[lane + 32], b2 = kr1[lane + 64], b3 = kr1[lane + 96];
        float4 c0 = kr2[lane], c1 = kr2[lane + 32], c2 = kr2[lane + 64], c3 = kr2[lane + 96];
        float4 d0 = kr3[lane], d1 = kr3[lane + 32], d2 = kr3[lane + 64], d3 = kr3[lane + 96];

        float s0 = dot16(a0, a1, a2, a3, q0, q1, q2, q3);
        float s1 = dot16(b0, b1, b2, b3, q0, q1, q2, q3);
        float s2 = dot16(c0, c1, c2, c3, q0, q1, q2, q3);
        float s3 = dot16(d0, d1, d2, d3, q0, q1, q2, q3);

        #pragma unroll
        for (int m = 16; m > 0; m >>= 1) {
            s0 += __shfl_xor_sync(0xFFFFFFFFu, s0, m);
            s1 += __shfl_xor_sync(0xFFFFFFFFu, s1, m);
            s2 += __shfl_xor_sync(0xFFFFFFFFu, s2, m);
            s3 += __shfl_xor_sync(0xFFFFFFFFu, s3, m);
        }
        const int bl = it * ROWS_PER_ITER;
        if (lane == bl + 0) mylogit = s0;
        if (lane == bl + 1) mylogit = s1;
        if (lane == bl + 2) mylogit = s2;
        if (lane == bl + 3) mylogit = s3;
    }

    // ---- warp-level max + sum(exp(l - wmax)) ----
    float wmax = mylogit;
    #pragma unroll
    for (int m = 16; m > 0; m >>= 1)
        wmax = fmaxf(wmax, __shfl_xor_sync(0xFFFFFFFFu, wmax, m));
    float wsum = __expf(mylogit - wmax);
    #pragma unroll
    for (int m = 16; m > 0; m >>= 1)
        wsum += __shfl_xor_sync(0xFFFFFFFFu, wsum, m);

    // ---- block combine ----
    __shared__ float s_wmax[WARPS];
    __shared__ float s_wsum[WARPS];
    __shared__ int   s_tiecnt;
    __shared__ int   s_tieidx[BTIES];
    __shared__ float s_bmax;
    __shared__ int   s_islast;

    if (lane == 0) { s_wmax[wid] = wmax; s_wsum[wid] = wsum; }
    if (tid == 0) s_tiecnt = 0;
    __syncthreads();

    if (tid == 0) {
        float bmax = -INFINITY;
        #pragma unroll
        for (int w = 0; w < WARPS; ++w) bmax = fmaxf(bmax, s_wmax[w]);
        float bsum = 0.f;
        #pragma unroll
        for (int w = 0; w < WARPS; ++w) bsum += s_wsum[w] * __expf(s_wmax[w] - bmax);
        s_bmax = bmax;
        g_blockmax[blockIdx.x] = bmax;
        g_blocksum[blockIdx.x] = bsum;
    }
    __syncthreads();

    // ties against the block max (bit-exact; max came from these same values)
    if (mylogit == s_bmax) {
        int p = atomicAdd(&s_tiecnt, 1);
        if (p < BTIES) s_tieidx[p] = wbase + lane;
    }
    __syncthreads();

    if (tid == 0) {
        int c = s_tiecnt; if (c > BTIES) c = BTIES;
        g_btiecnt[blockIdx.x] = c;
        for (int j = 0; j < c; ++j) g_btieidx[blockIdx.x * BTIES + j] = s_tieidx[j];
        __threadfence();
        unsigned int ticket = atomicAdd(&g_done, 1u);
        s_islast = (ticket == GRID - 1);
    }
    __syncthreads();
    if (!s_islast) return;

    // ================= last block: final reduction + output =================
    __shared__ float s_red[BLOCK / 32];
    __shared__ float s_M, s_Z;
    __shared__ int   f_cnt;
    __shared__ int   f_idx[MAX_TIES];

    // global max M
    float m = -INFINITY;
    for (int b = tid; b < GRID; b += BLOCK) m = fmaxf(m, g_blockmax[b]);
    #pragma unroll
    for (int k = 16; k > 0; k >>= 1) m = fmaxf(m, __shfl_xor_sync(0xFFFFFFFFu, m, k));
    if (lane == 0) s_red[wid] = m;
    if (tid == 0) f_cnt = 0;
    __syncthreads();
    if (tid == 0) {
        float M = -INFINITY;
        #pragma unroll
        for (int w = 0; w < WARPS; ++w) M = fmaxf(M, s_red[w]);
        s_M = M;
    }
    __syncthreads();
    const float M = s_M;

    // Z = sum blocksum_b * exp(bmax_b - M);  gather global tie indices
    float z = 0.f;
    for (int b = tid; b < GRID; b += BLOCK) {
        float bm = g_blockmax[b];
        z += g_blocksum[b] * __expf(bm - M);
        if (bm == M) {
            int c = g_btiecnt[b];
            for (int j = 0; j < c; ++j) {
                int p = atomicAdd(&f_cnt, 1);
                if (p < MAX_TIES) f_idx[p] = g_btieidx[b * BTIES + j];
            }
        }
    }
    #pragma unroll
    for (int k = 16; k > 0; k >>= 1) z += __shfl_xor_sync(0xFFFFFFFFu, z, k);
    if (lane == 0) s_red[wid] = z;
    __syncthreads();
    if (tid == 0) {
        float Z = 0.f;
        #pragma unroll
        for (int w = 0; w < WARPS; ++w) Z += s_red[w];
        s_Z = Z;
        g_done = 0;   // reset for next (graph-replayed) launch
    }
    __syncthreads();

    // out[v] = (1/Z) * sum over tied rows of values[row][v]
    const float invZ = 1.0f / s_Z;
    int cnt = f_cnt; if (cnt > MAX_TIES) cnt = MAX_TIES;
    for (int v = tid; v < V_DIM; v += BLOCK) {
        float acc = 0.f;
        for (int j = 0; j < cnt; ++j)
            acc += values[(size_t)f_idx[j] * V_DIM + v];
        out[v] = acc * invZ;
    }
}

// ---------------------------------------------------------------------------
extern "C" void kernel_launch(void* const* d_in, const int* in_sizes, int n_in,
                              void* d_out, int out_size)
{
    const float* query  = (const float*)d_in[0];  // [512]
    const float* keys   = (const float*)d_in[1];  // [262144, 512]
    const float* values = (const float*)d_in[2];  // [262144, 512]
    float* out = (float*)d_out;                   // [512]

    fused_kernel<<<GRID, BLOCK>>>(query, keys, values, out);
}

// round 14
// speedup vs baseline: 1.1945x; 1.0449x over previous
#include <cuda_runtime.h>
#include <math.h>

// Problem shape (fixed by reference)
#define N_ROWS 262144
#define D_DIM  512
#define V_DIM  512

#define GRID   456                      // 152 SMs x 3 resident CTAs -> single wave
#define BLOCK  256
#define WARPS  (BLOCK / 32)
#define TOTAL_WARPS (GRID * WARPS)      // 3648
#define N_GROUPS (N_ROWS / 4)           // 65536 groups of 4 rows

#define BTIES     4     // tie indices kept per block
#define MAX_TIES 16     // tie indices kept globally

// ---- device scratch (static zero-init; g_done reset by last block) ----
__device__ float g_blockmax[GRID];
__device__ float g_blocksum[GRID];
__device__ int   g_btiecnt[GRID];
__device__ int   g_btieidx[GRID * BTIES];
__device__ unsigned int g_done;   // zero-initialized; reset to 0 each launch

__device__ __forceinline__ float dot16(float4 a0, float4 a1, float4 a2, float4 a3,
                                       float4 q0, float4 q1, float4 q2, float4 q3)
{
    float s = 0.f;
    s = fmaf(a0.x, q0.x, s); s = fmaf(a0.y, q0.y, s);
    s = fmaf(a0.z, q0.z, s); s = fmaf(a0.w, q0.w, s);
    s = fmaf(a1.x, q1.x, s); s = fmaf(a1.y, q1.y, s);
    s = fmaf(a1.z, q1.z, s); s = fmaf(a1.w, q1.w, s);
    s = fmaf(a2.x, q2.x, s); s = fmaf(a2.y, q2.y, s);
    s = fmaf(a2.z, q2.z, s); s = fmaf(a2.w, q2.w, s);
    s = fmaf(a3.x, q3.x, s); s = fmaf(a3.y, q3.y, s);
    s = fmaf(a3.z, q3.z, s); s = fmaf(a3.w, q3.w, s);
    return s;
}

__global__ __launch_bounds__(BLOCK, 3) void fused_kernel(
    const float* __restrict__ query,
    const float* __restrict__ keys,
    const float* __restrict__ values,
    float* __restrict__ out)
{
    const int tid   = threadIdx.x;
    const int lane  = tid & 31;
    const int wid   = tid >> 5;
    const int gwarp = blockIdx.x * WARPS + wid;

    // Query register-resident: lane l owns q 16B-chunks l, l+32, l+64, l+96
    const float4* q4 = reinterpret_cast<const float4*>(query);
    const float4 q0 = q4[lane];
    const float4 q1 = q4[lane + 32];
    const float4 q2 = q4[lane + 64];
    const float4 q3 = q4[lane + 96];

    // per-lane online softmax state (only lanes 0..3 accumulate)
    float m = -INFINITY, s = 0.f;
    int   idx = -1, idx2 = -1;

    #pragma unroll 1
    for (int g = gwarp; g < N_GROUPS; g += TOTAL_WARPS) {
        const int row = g * 4;
        const float4* kr0 = reinterpret_cast<const float4*>(keys + (size_t)(row + 0) * D_DIM);
        const float4* kr1 = reinterpret_cast<const float4*>(keys + (size_t)(row + 1) * D_DIM);
        const float4* kr2 = reinterpret_cast<const float4*>(keys + (size_t)(row + 2) * D_DIM);
        const float4* kr3 = reinterpret_cast<const float4*>(keys + (size_t)(row + 3) * D_DIM);

        float4 a0 = kr0[lane], a1 = kr0[lane + 32], a2 = kr0[lane + 64], a3 = kr0[lane + 96];
        float4 b0 = kr1[lane], b1 = kr1[lane + 32], b2 = kr1[lane + 64], b3 = kr1[lane + 96];
        float4 c0 = kr2[lane], c1 = kr2[lane + 32], c2 = kr2[lane + 64], c3 = kr2[lane + 96];
        float4 d0 = kr3[lane], d1 = kr3[lane + 32], d2 = kr3[lane + 64], d3 = kr3[lane + 96];

        float s0 = dot16(a0, a1, a2, a3, q0, q1, q2, q3);
        float s1 = dot16(b0, b1, b2, b3, q0, q1, q2, q3);
        float s2 = dot16(c0, c1, c2, c3, q0, q1, q2, q3);
        float s3 = dot16(d0, d1, d2, d3, q0, q1, q2, q3);

        // ---- transposed reduction: 6 shuffles total ----
        // after xor1: even lanes hold row0/row2 pair-partials, odd lanes row1/row3
        float u01 = (lane & 1) ? s1 : s0;
        float v01 = (lane & 1) ? s0 : s1;
        u01 += __shfl_xor_sync(0xFFFFFFFFu, v01, 1);
        float u23 = (lane & 1) ? s3 : s2;
        float v23 = (lane & 1) ? s2 : s3;
        u23 += __shfl_xor_sync(0xFFFFFFFFu, v23, 1);
        // after xor2: lane l holds row (l&3), partial over its 4-lane group
        float u = (lane & 2) ? u23 : u01;
        float v = (lane & 2) ? u01 : u23;
        u += __shfl_xor_sync(0xFFFFFFFFu, v, 2);
        // complete across the 8 groups
        u += __shfl_xor_sync(0xFFFFFFFFu, u, 4);
        u += __shfl_xor_sync(0xFFFFFFFFu, u, 8);
        u += __shfl_xor_sync(0xFFFFFFFFu, u, 16);
        // u on lane l == full logit of row (row + (l&3)), replicated x8

        if (lane < 4) {
            float x = u;
            if (x > m) {
                s = s * __expf(m - x) + 1.0f;   // expf(-inf)=0 on first hit
                m = x; idx = row + lane; idx2 = -1;
            } else if (x == m) {
                s += 1.0f; idx2 = row + lane;
            } else {
                s += __expf(x - m);
            }
        }
    }

    // ---- warp-level guarded online merge of (m, s) ----
    float wm = m, ws = s;
    #pragma unroll
    for (int k = 16; k > 0; k >>= 1) {
        float om = __shfl_xor_sync(0xFFFFFFFFu, wm, k);
        float os = __shfl_xor_sync(0xFFFFFFFFu, ws, k);
        float nm = fmaxf(wm, om);
        float fa = (wm == nm) ? 1.0f : __expf(wm - nm);
        float fb = (om == nm) ? 1.0f : __expf(om - nm);
        ws = ws * fa + os * fb;
        wm = nm;
    }

    // ---- block combine ----
    __shared__ float s_wmax[WARPS];
    __shared__ float s_wsum[WARPS];
    __shared__ int   s_tiecnt;
    __shared__ int   s_tieidx[BTIES];
    __shared__ float s_bmax;
    __shared__ int   s_islast;

    if (lane == 0) { s_wmax[wid] = wm; s_wsum[wid] = ws; }
    if (tid == 0) s_tiecnt = 0;
    __syncthreads();

    if (tid == 0) {
        float bmax = -INFINITY;
        #pragma unroll
        for (int w = 0; w < WARPS; ++w) bmax = fmaxf(bmax, s_wmax[w]);
        float bsum = 0.f;
        #pragma unroll
        for (int w = 0; w < WARPS; ++w) bsum += s_wsum[w] * __expf(s_wmax[w] - bmax);
        s_bmax = bmax;
        g_blockmax[blockIdx.x] = bmax;
        g_blocksum[blockIdx.x] = bsum;
    }
    __syncthreads();

    // tie recording against block max (bit-exact: same stored values)
    if (m == s_bmax) {
        int p = atomicAdd(&s_tiecnt, 1);
        if (p < BTIES) s_tieidx[p] = idx;
        if (idx2 >= 0) {
            int p2 = atomicAdd(&s_tiecnt, 1);
            if (p2 < BTIES) s_tieidx[p2] = idx2;
        }
    }
    __syncthreads();

    if (tid == 0) {
        int c = s_tiecnt; if (c > BTIES) c = BTIES;
        g_btiecnt[blockIdx.x] = c;
        for (int j = 0; j < c; ++j) g_btieidx[blockIdx.x * BTIES + j] = s_tieidx[j];
        __threadfence();
        unsigned int ticket = atomicAdd(&g_done, 1u);
        s_islast = (ticket == GRID - 1);
    }
    __syncthreads();
    if (!s_islast) return;

    // ================= last block: final reduction + output =================
    __shared__ float s_red[WARPS];
    __shared__ float s_M, s_Z;
    __shared__ int   f_cnt;
    __shared__ int   f_idx[MAX_TIES];

    float gm = -INFINITY;
    for (int b = tid; b < GRID; b += BLOCK) gm = fmaxf(gm, g_blockmax[b]);
    #pragma unroll
    for (int k = 16; k > 0; k >>= 1) gm = fmaxf(gm, __shfl_xor_sync(0xFFFFFFFFu, gm, k));
    if (lane == 0) s_red[wid] = gm;
    if (tid == 0) f_cnt = 0;
    __syncthreads();
    if (tid == 0) {
        float M = -INFINITY;
        #pragma unroll
        for (int w = 0; w < WARPS; ++w) M = fmaxf(M, s_red[w]);
        s_M = M;
    }
    __syncthreads();
    const float M = s_M;

    float z = 0.f;
    for (int b = tid; b < GRID; b += BLOCK) {
        float bm = g_blockmax[b];
        z += g_blocksum[b] * __expf(bm - M);
        if (bm == M) {
            int c = g_btiecnt[b];
            for (int j = 0; j < c; ++j) {
                int p = atomicAdd(&f_cnt, 1);
                if (p < MAX_TIES) f_idx[p] = g_btieidx[b * BTIES + j];
            }
        }
    }
    #pragma unroll
    for (int k = 16; k > 0; k >>= 1) z += __shfl_xor_sync(0xFFFFFFFFu, z, k);
    if (lane == 0) s_red[wid] = z;
    __syncthreads();
    if (tid == 0) {
        float Z = 0.f;
        #pragma unroll
        for (int w = 0; w < WARPS; ++w) Z += s_red[w];
        s_Z = Z;
        g_done = 0;   // reset for next graph replay
    }
    __syncthreads();

    const float invZ = 1.0f / s_Z;
    int cnt = f_cnt; if (cnt > MAX_TIES) cnt = MAX_TIES;
    for (int v = tid; v < V_DIM; v += BLOCK) {
        float acc = 0.f;
        for (int j = 0; j < cnt; ++j)
            acc += values[(size_t)f_idx[j] * V_DIM + v];
        out[v] = acc * invZ;
    }
}

// ---------------------------------------------------------------------------
extern "C" void kernel_launch(void* const* d_in, const int* in_sizes, int n_in,
                              void* d_out, int out_size)
{
    const float* query  = (const float*)d_in[0];  // [512]
    const float* keys   = (const float*)d_in[1];  // [262144, 512]
    const float* values = (const float*)d_in[2];  // [262144, 512]
    float* out = (float*)d_out;                   // [512]

    fused_kernel<<<GRID, BLOCK>>>(query, keys, values, out);
}

// round 15
// speedup vs baseline: 1.1949x; 1.0004x over previous
#include <cuda_runtime.h>
#include <math.h>

// Problem shape (fixed by reference)
#define N_ROWS 262144
#define D_DIM  512
#define V_DIM  512

#define GRID   456                      // 152 SMs x 3 resident CTAs -> single wave
#define BLOCK  256
#define WARPS  (BLOCK / 32)
#define TOTAL_WARPS (GRID * WARPS)      // 3648
#define N_GROUPS (N_ROWS / 4)           // 65536 groups of 4 rows

#define BTIES     4     // tie indices kept per block
#define MAX_TIES 16     // tie indices kept globally

// ---- device scratch (static zero-init; g_done reset by last block) ----
__device__ float g_blockmax[GRID];
__device__ float g_blocksum[GRID];
__device__ int   g_btiecnt[GRID];
__device__ int   g_btieidx[GRID * BTIES];
__device__ unsigned int g_done;   // zero-initialized; reset to 0 each launch

__device__ __forceinline__ float dot16(float4 a0, float4 a1, float4 a2, float4 a3,
                                       float4 q0, float4 q1, float4 q2, float4 q3)
{
    float s = 0.f;
    s = fmaf(a0.x, q0.x, s); s = fmaf(a0.y, q0.y, s);
    s = fmaf(a0.z, q0.z, s); s = fmaf(a0.w, q0.w, s);
    s = fmaf(a1.x, q1.x, s); s = fmaf(a1.y, q1.y, s);
    s = fmaf(a1.z, q1.z, s); s = fmaf(a1.w, q1.w, s);
    s = fmaf(a2.x, q2.x, s); s = fmaf(a2.y, q2.y, s);
    s = fmaf(a2.z, q2.z, s); s = fmaf(a2.w, q2.w, s);
    s = fmaf(a3.x, q3.x, s); s = fmaf(a3.y, q3.y, s);
    s = fmaf(a3.z, q3.z, s); s = fmaf(a3.w, q3.w, s);
    return s;
}

__global__ __launch_bounds__(BLOCK, 3) void fused_kernel(
    const float* __restrict__ query,
    const float* __restrict__ keys,
    const float* __restrict__ values,
    float* __restrict__ out)
{
    const int tid   = threadIdx.x;
    const int lane  = tid & 31;
    const int wid   = tid >> 5;
    const int gwarp = blockIdx.x * WARPS + wid;

    // Query register-resident: lane l owns q 16B-chunks l, l+32, l+64, l+96
    const float4* q4 = reinterpret_cast<const float4*>(query);
    const float4 q0 = q4[lane];
    const float4 q1 = q4[lane + 32];
    const float4 q2 = q4[lane + 64];
    const float4 q3 = q4[lane + 96];

    // per-lane online softmax state (only lanes 0..3 accumulate)
    float m = -INFINITY, s = 0.f;
    int   idx = -1, idx2 = -1;

    #pragma unroll 1
    for (int g = gwarp; g < N_GROUPS; g += TOTAL_WARPS) {
        const int row = g * 4;
        const float4* kr0 = reinterpret_cast<const float4*>(keys + (size_t)(row + 0) * D_DIM);
        const float4* kr1 = reinterpret_cast<const float4*>(keys + (size_t)(row + 1) * D_DIM);
        const float4* kr2 = reinterpret_cast<const float4*>(keys + (size_t)(row + 2) * D_DIM);
        const float4* kr3 = reinterpret_cast<const float4*>(keys + (size_t)(row + 3) * D_DIM);

        float4 a0 = kr0[lane], a1 = kr0[lane + 32], a2 = kr0[lane + 64], a3 = kr0[lane + 96];
        float4 b0 = kr1[lane], b1 = kr1[lane + 32], b2 = kr1[lane + 64], b3 = kr1[lane + 96];
        float4 c0 = kr2[lane], c1 = kr2[lane + 32], c2 = kr2[lane + 64], c3 = kr2[lane + 96];
        float4 d0 = kr3[lane], d1 = kr3[lane + 32], d2 = kr3[lane + 64], d3 = kr3[lane + 96];

        float s0 = dot16(a0, a1, a2, a3, q0, q1, q2, q3);
        float s1 = dot16(b0, b1, b2, b3, q0, q1, q2, q3);
        float s2 = dot16(c0, c1, c2, c3, q0, q1, q2, q3);
        float s3 = dot16(d0, d1, d2, d3, q0, q1, q2, q3);

        // ---- transposed reduction: 6 shuffles total ----
        // after xor1: even lanes hold row0/row2 pair-partials, odd lanes row1/row3
        float u01 = (lane & 1) ? s1 : s0;
        float v01 = (lane & 1) ? s0 : s1;
        u01 += __shfl_xor_sync(0xFFFFFFFFu, v01, 1);
        float u23 = (lane & 1) ? s3 : s2;
        float v23 = (lane & 1) ? s2 : s3;
        u23 += __shfl_xor_sync(0xFFFFFFFFu, v23, 1);
        // after xor2: lane l holds row (l&3), partial over its 4-lane group
        float u = (lane & 2) ? u23 : u01;
        float v = (lane & 2) ? u01 : u23;
        u += __shfl_xor_sync(0xFFFFFFFFu, v, 2);
        // complete across the 8 groups
        u += __shfl_xor_sync(0xFFFFFFFFu, u, 4);
        u += __shfl_xor_sync(0xFFFFFFFFu, u, 8);
        u += __shfl_xor_sync(0xFFFFFFFFu, u, 16);
        // u on lane l == full logit of row (row + (l&3)), replicated x8

        if (lane < 4) {
            float x = u;
            if (x > m) {
                s = s * __expf(m - x) + 1.0f;   // expf(-inf)=0 on first hit
                m = x; idx = row + lane; idx2 = -1;
            } else if (x == m) {
                s += 1.0f; idx2 = row + lane;
            } else {
                s += __expf(x - m);
            }
        }
    }

    // ---- warp-level guarded online merge of (m, s) ----
    float wm = m, ws = s;
    #pragma unroll
    for (int k = 16; k > 0; k >>= 1) {
        float om = __shfl_xor_sync(0xFFFFFFFFu, wm, k);
        float os = __shfl_xor_sync(0xFFFFFFFFu, ws, k);
        float nm = fmaxf(wm, om);
        float fa = (wm == nm) ? 1.0f : __expf(wm - nm);
        float fb = (om == nm) ? 1.0f : __expf(om - nm);
        ws = ws * fa + os * fb;
        wm = nm;
    }

    // ---- block combine ----
    __shared__ float s_wmax[WARPS];
    __shared__ float s_wsum[WARPS];
    __shared__ int   s_tiecnt;
    __shared__ int   s_tieidx[BTIES];
    __shared__ float s_bmax;
    __shared__ int   s_islast;

    if (lane == 0) { s_wmax[wid] = wm; s_wsum[wid] = ws; }
    if (tid == 0) s_tiecnt = 0;
    __syncthreads();

    if (tid == 0) {
        float bmax = -INFINITY;
        #pragma unroll
        for (int w = 0; w < WARPS; ++w) bmax = fmaxf(bmax, s_wmax[w]);
        float bsum = 0.f;
        #pragma unroll
        for (int w = 0; w < WARPS; ++w) bsum += s_wsum[w] * __expf(s_wmax[w] - bmax);
        s_bmax = bmax;
        g_blockmax[blockIdx.x] = bmax;
        g_blocksum[blockIdx.x] = bsum;
    }
    __syncthreads();

    // tie recording against block max (bit-exact: same stored values)
    if (m == s_bmax) {
        int p = atomicAdd(&s_tiecnt, 1);
        if (p < BTIES) s_tieidx[p] = idx;
        if (idx2 >= 0) {
            int p2 = atomicAdd(&s_tiecnt, 1);
            if (p2 < BTIES) s_tieidx[p2] = idx2;
        }
    }
    __syncthreads();

    if (tid == 0) {
        int c = s_tiecnt; if (c > BTIES) c = BTIES;
        g_btiecnt[blockIdx.x] = c;
        for (int j = 0; j < c; ++j) g_btieidx[blockIdx.x * BTIES + j] = s_tieidx[j];
        __threadfence();
        unsigned int ticket = atomicAdd(&g_done, 1u);
        s_islast = (ticket == GRID - 1);
    }
    __syncthreads();
    if (!s_islast) return;

    // ================= last block: final reduction + output =================
    __shared__ float s_red[WARPS];
    __shared__ float s_M, s_Z;
    __shared__ int   f_cnt;
    __shared__ int   f_idx[MAX_TIES];

    float gm = -INFINITY;
    for (int b = tid; b < GRID; b += BLOCK) gm = fmaxf(gm, g_blockmax[b]);
    #pragma unroll
    for (int k = 16; k > 0; k >>= 1) gm = fmaxf(gm, __shfl_xor_sync(0xFFFFFFFFu, gm, k));
    if (lane == 0) s_red[wid] = gm;
    if (tid == 0) f_cnt = 0;
    __syncthreads();
    if (tid == 0) {
        float M = -INFINITY;
        #pragma unroll
        for (int w = 0; w < WARPS; ++w) M = fmaxf(M, s_red[w]);
        s_M = M;
    }
    __syncthreads();
    const float M = s_M;

    float z = 0.f;
    for (int b = tid; b < GRID; b += BLOCK) {
        float bm = g_blockmax[b];
        z += g_blocksum[b] * __expf(bm - M);
        if (bm == M) {
            int c = g_btiecnt[b];
            for (int j = 0; j < c; ++j) {
                int p = atomicAdd(&f_cnt, 1);
                if (p < MAX_TIES) f_idx[p] = g_btieidx[b * BTIES + j];
            }
        }
    }
    #pragma unroll
    for (int k = 16; k > 0; k >>= 1) z += __shfl_xor_sync(0xFFFFFFFFu, z, k);
    if (lane == 0) s_red[wid] = z;
    __syncthreads();
    if (tid == 0) {
        float Z = 0.f;
        #pragma unroll
        for (int w = 0; w < WARPS; ++w) Z += s_red[w];
        s_Z = Z;
        g_done = 0;   // reset for next graph replay
    }
    __syncthreads();

    const float invZ = 1.0f / s_Z;
    int cnt = f_cnt; if (cnt > MAX_TIES) cnt = MAX_TIES;
    for (int v = tid; v < V_DIM; v += BLOCK) {
        float acc = 0.f;
        for (int j = 0; j < cnt; ++j)
            acc += values[(size_t)f_idx[j] * V_DIM + v];
        out[v] = acc * invZ;
    }
}

// ---------------------------------------------------------------------------
extern "C" void kernel_launch(void* const* d_in, const int* in_sizes, int n_in,
                              void* d_out, int out_size)
{
    const float* query  = (const float*)d_in[0];  // [512]
    const float* keys   = (const float*)d_in[1];  // [262144, 512]
    const float* values = (const float*)d_in[2];  // [262144, 512]
    float* out = (float*)d_out;                   // [512]

    fused_kernel<<<GRID, BLOCK>>>(query, keys, values, out);
}